// round 7
// baseline (speedup 1.0000x reference)
#include <cuda_runtime.h>
#include <math.h>

#define NPATCH 196
#define IPB    2                 // images per block
#define BLOCK  (IPB * 64)        // 2 warps per image

__global__ __launch_bounds__(BLOCK)
void quanv_fused_kernel(const float* __restrict__ x,
                        const float* __restrict__ emb_W,
                        const float* __restrict__ emb_b,
                        const float* __restrict__ q_params,
                        const float* __restrict__ lin_W,
                        const float* __restrict__ lin_b,
                        float* __restrict__ out,
                        int B)
{
    __shared__ float shalf[IPB][2][10];

    const int warp = threadIdx.x >> 5;
    const int lane = threadIdx.x & 31;
    const int img  = warp >> 1;        // image slot within block
    const int h    = warp & 1;         // which half of the patches
    const int b    = blockIdx.x * IPB + img;
    const bool valid = (b < B);
    const int bs = valid ? b : 0;      // safe base; stores gated by `valid`

    // ---- uniform circuit constants (broadcast loads + MUFU) ----
    const float Kc0 = __cosf(q_params[0]);           // cos q0
    const float Kq1 = q_params[1];                   // q1
    float s4, c4;
    __sincosf(q_params[4], &s4, &c4);                // sin/cos q4
    const float Ks4 = s4 * __cosf(q_params[2]);      // sin q4 * cos q2
    const float Kc3 = __cosf(q_params[3]);           // cos q3

    const float4 W0 = __ldg((const float4*)(emb_W + 0));
    const float4 W1 = __ldg((const float4*)(emb_W + 4));
    const float4 W2 = __ldg((const float4*)(emb_W + 8));
    const float4 W3 = __ldg((const float4*)(emb_W + 12));
    const float4 eb = __ldg((const float4*)emb_b);

    const float*  xb  = x + bs * 784;
    const float4* lw4 = (const float4*)lin_W;   // lin_W[c*784 + 4*p] == lw4[c*196 + p]

    float acc[10];
#pragma unroll
    for (int c = 0; c < 10; c++) acc[c] = 0.f;

    // half h handles p = lane + 32h + 64k, k=0..2; half 0 lanes 0..3 take tail 192..195
#pragma unroll
    for (int k = 0; k < 4; k++) {
        const int p = lane + 32 * h + 64 * k;
        if (k == 3 && p >= NPATCH) break;

        const int pr = p / 14, pc = p % 14;
        const float2 top = *(const float2*)(xb + (2 * pr) * 28 + 2 * pc);
        const float2 bot = *(const float2*)(xb + (2 * pr + 1) * 28 + 2 * pc);

        const float a0 = fmaf(top.x, W0.x, fmaf(top.y, W0.y, fmaf(bot.x, W0.z, fmaf(bot.y, W0.w, eb.x))));
        const float a1 = fmaf(top.x, W1.x, fmaf(top.y, W1.y, fmaf(bot.x, W1.z, fmaf(bot.y, W1.w, eb.y))));
        const float a2 = fmaf(top.x, W2.x, fmaf(top.y, W2.y, fmaf(bot.x, W2.z, fmaf(bot.y, W2.w, eb.z))));
        const float a3 = fmaf(top.x, W3.x, fmaf(top.y, W3.y, fmaf(bot.x, W3.z, fmaf(bot.y, W3.w, eb.w))));

        // closed-form <Z_w> of the 4-qubit circuit
        const float ca0  = __cosf(a0);
        const float ca1q = __cosf(a1 + Kq1);
        float sa2, ca2, sa3, ca3;
        __sincosf(a2, &sa2, &ca2);
        __sincosf(a3, &sa3, &ca3);

        const float e0 = Kc0 * ca0;
        const float e1 = e0 * ca1q;
        const float e2 = e1 * fmaf(c4, ca2, -Ks4 * sa2 * sa3);
        const float e3 = ca2 * (Kc3 * ca3);

        // accumulate partial logits (coalesced 512B per channel per round)
#pragma unroll
        for (int c = 0; c < 10; c++) {
            const float4 w = __ldg(&lw4[c * NPATCH + p]);
            acc[c] = fmaf(e0, w.x, fmaf(e1, w.y, fmaf(e2, w.z, fmaf(e3, w.w, acc[c]))));
        }
    }

    // ---- intra-warp xor-butterfly: every lane ends with this half's 10 sums ----
#pragma unroll
    for (int off = 16; off > 0; off >>= 1)
#pragma unroll
        for (int c = 0; c < 10; c++)
            acc[c] += __shfl_xor_sync(0xffffffffu, acc[c], off);

    // predicated selection chain (no dynamic indexing -> no spill)
    {
        float v = acc[0];
#pragma unroll
        for (int c = 1; c < 10; c++) if (lane == c) v = acc[c];
        if (lane < 10) shalf[img][h][lane] = v;
    }
    __syncthreads();

    // ---- half 0 finishes: combine halves, log_softmax, coalesced store ----
    if (h == 0 && lane < 10 && valid) {
        float lg[10];
#pragma unroll
        for (int c = 0; c < 10; c++)
            lg[c] = shalf[img][0][c] + shalf[img][1][c] + __ldg(&lin_b[c]);

        float mx = lg[0];
#pragma unroll
        for (int c = 1; c < 10; c++) mx = fmaxf(mx, lg[c]);
        float se = 0.f;
#pragma unroll
        for (int c = 0; c < 10; c++) se += __expf(lg[c] - mx);
        const float lse = mx + __logf(se);

        float v = lg[0];
#pragma unroll
        for (int c = 1; c < 10; c++) if (lane == c) v = lg[c];
        out[b * 10 + lane] = v - lse;
    }
}

extern "C" void kernel_launch(void* const* d_in, const int* in_sizes, int n_in,
                              void* d_out, int out_size)
{
    const float* x        = (const float*)d_in[0];
    const float* emb_W    = (const float*)d_in[1];
    const float* emb_b    = (const float*)d_in[2];
    const float* q_params = (const float*)d_in[3];
    const float* lin_W    = (const float*)d_in[4];
    const float* lin_b    = (const float*)d_in[5];
    float* out = (float*)d_out;

    const int B = in_sizes[0] / 784;
    const int grid = (B + IPB - 1) / IPB;
    quanv_fused_kernel<<<grid, BLOCK>>>(x, emb_W, emb_b, q_params, lin_W, lin_b, out, B);
}

// round 8
// speedup vs baseline: 1.2099x; 1.2099x over previous
#include <cuda_runtime.h>
#include <math.h>
#include <cstdint>

#define NPATCH 196
#define WPB    4      // images (warps) per block
#define BLOCK  (WPB * 32)

#define FMA_F32X2(d, a, b, c) \
    asm("fma.rn.f32x2 %0, %1, %2, %3;" : "=l"(d) : "l"(a), "l"(b), "l"(c))
#define PACK_F32X2(out, lo, hi) \
    asm("mov.b64 %0, {%1, %2};" : "=l"(out) : "f"(lo), "f"(hi))
#define UNPACK_F32X2(lo, hi, in) \
    asm("mov.b64 {%0, %1}, %2;" : "=f"(lo), "=f"(hi) : "l"(in))

__global__ __launch_bounds__(BLOCK)
void quanv_fused_kernel(const float* __restrict__ x,
                        const float* __restrict__ emb_W,
                        const float* __restrict__ emb_b,
                        const float* __restrict__ q_params,
                        const float* __restrict__ lin_W,
                        const float* __restrict__ lin_b,
                        float* __restrict__ out,
                        int B)
{
    const int warp = threadIdx.x >> 5;
    const int lane = threadIdx.x & 31;
    const int b    = blockIdx.x * WPB + warp;
    if (b >= B) return;

    // ---- uniform circuit constants (broadcast loads + MUFU) ----
    const float Kc0 = __cosf(q_params[0]);           // cos q0
    const float Kq1 = q_params[1];                   // q1
    float s4, c4;
    __sincosf(q_params[4], &s4, &c4);                // sin/cos q4
    const float Ks4 = s4 * __cosf(q_params[2]);      // sin q4 * cos q2
    const float Kc3 = __cosf(q_params[3]);           // cos q3

    const float4 W0 = __ldg((const float4*)(emb_W + 0));
    const float4 W1 = __ldg((const float4*)(emb_W + 4));
    const float4 W2 = __ldg((const float4*)(emb_W + 8));
    const float4 W3 = __ldg((const float4*)(emb_W + 12));
    const float4 eb = __ldg((const float4*)emb_b);

    const float*   xb  = x + b * 784;
    const double2* lw2 = (const double2*)lin_W;  // lw2[c*196 + p] = bits of lin_W[c*784+4p ..]

    // packed accumulators: lo accumulates e0*w.x + e2*w.z ; hi: e1*w.y + e3*w.w
    unsigned long long acc2[10];
#pragma unroll
    for (int c = 0; c < 10; c++) acc2[c] = 0ull;

    // lane handles patches p = lane, lane+32, ... (6 full rounds + tail for lanes 0..3)
#pragma unroll
    for (int k = 0; k < 7; k++) {
        const int p = lane + 32 * k;
        if (k == 6 && p >= NPATCH) break;          // only lanes 0..3 do round 7

        const int pr = p / 14, pc = p % 14;
        const float2 top = *(const float2*)(xb + (2 * pr) * 28 + 2 * pc);
        const float2 bot = *(const float2*)(xb + (2 * pr + 1) * 28 + 2 * pc);

        const float a0 = fmaf(top.x, W0.x, fmaf(top.y, W0.y, fmaf(bot.x, W0.z, fmaf(bot.y, W0.w, eb.x))));
        const float a1 = fmaf(top.x, W1.x, fmaf(top.y, W1.y, fmaf(bot.x, W1.z, fmaf(bot.y, W1.w, eb.y))));
        const float a2 = fmaf(top.x, W2.x, fmaf(top.y, W2.y, fmaf(bot.x, W2.z, fmaf(bot.y, W2.w, eb.z))));
        const float a3 = fmaf(top.x, W3.x, fmaf(top.y, W3.y, fmaf(bot.x, W3.z, fmaf(bot.y, W3.w, eb.w))));

        // closed-form <Z_w> of the 4-qubit circuit
        const float ca0  = __cosf(a0);
        const float ca1q = __cosf(a1 + Kq1);
        float sa2, ca2, sa3, ca3;
        __sincosf(a2, &sa2, &ca2);
        __sincosf(a3, &sa3, &ca3);

        const float e0 = Kc0 * ca0;
        const float e1 = e0 * ca1q;
        const float e2 = e1 * fmaf(c4, ca2, -Ks4 * sa2 * sa3);
        const float e3 = ca2 * (Kc3 * ca3);

        // pack feature pairs once per round
        unsigned long long E01, E23;
        PACK_F32X2(E01, e0, e1);
        PACK_F32X2(E23, e2, e3);

        // packed GEMV: 2 FFMA2 per channel (LDG.128 gives aligned 64-bit w pairs)
#pragma unroll
        for (int c = 0; c < 10; c++) {
            const double2 wd = __ldg(&lw2[c * NPATCH + p]);
            const unsigned long long wxy = __double_as_longlong(wd.x);
            const unsigned long long wzw = __double_as_longlong(wd.y);
            FMA_F32X2(acc2[c], E23, wzw, acc2[c]);
            FMA_F32X2(acc2[c], E01, wxy, acc2[c]);
        }
    }

    // collapse packed pairs to scalar partial logits
    float acc[10];
#pragma unroll
    for (int c = 0; c < 10; c++) {
        float lo, hi;
        UNPACK_F32X2(lo, hi, acc2[c]);
        acc[c] = lo + hi;
    }

    // ---- xor-butterfly: every lane ends with the full 10 logit sums ----
#pragma unroll
    for (int off = 16; off > 0; off >>= 1)
#pragma unroll
        for (int c = 0; c < 10; c++)
            acc[c] += __shfl_xor_sync(0xffffffffu, acc[c], off);

    // ---- log_softmax, lanes 0..9 write coalesced ----
    if (lane < 10) {
        float lg[10];
#pragma unroll
        for (int c = 0; c < 10; c++) lg[c] = acc[c] + __ldg(&lin_b[c]);

        float mx = lg[0];
#pragma unroll
        for (int c = 1; c < 10; c++) mx = fmaxf(mx, lg[c]);
        float se = 0.f;
#pragma unroll
        for (int c = 0; c < 10; c++) se += __expf(lg[c] - mx);
        const float lse = mx + __logf(se);

        float v = lg[0];
#pragma unroll
        for (int c = 1; c < 10; c++) if (lane == c) v = lg[c];
        out[b * 10 + lane] = v - lse;
    }
}

extern "C" void kernel_launch(void* const* d_in, const int* in_sizes, int n_in,
                              void* d_out, int out_size)
{
    const float* x        = (const float*)d_in[0];
    const float* emb_W    = (const float*)d_in[1];
    const float* emb_b    = (const float*)d_in[2];
    const float* q_params = (const float*)d_in[3];
    const float* lin_W    = (const float*)d_in[4];
    const float* lin_b    = (const float*)d_in[5];
    float* out = (float*)d_out;

    const int B = in_sizes[0] / 784;
    const int grid = (B + WPB - 1) / WPB;
    quanv_fused_kernel<<<grid, BLOCK>>>(x, emb_W, emb_b, q_params, lin_W, lin_b, out, B);
}

// round 9
// speedup vs baseline: 1.2388x; 1.0239x over previous
#include <cuda_runtime.h>
#include <math.h>
#include <cstdint>

#define NPATCH 196
#define WPB    2      // images (warps) per block
#define BLOCK  (WPB * 32)

#define FMA_F32X2(d, a, b, c) \
    asm("fma.rn.f32x2 %0, %1, %2, %3;" : "=l"(d) : "l"(a), "l"(b), "l"(c))
#define PACK_F32X2(out, lo, hi) \
    asm("mov.b64 %0, {%1, %2};" : "=l"(out) : "f"(lo), "f"(hi))
#define UNPACK_F32X2(lo, hi, in) \
    asm("mov.b64 {%0, %1}, %2;" : "=f"(lo), "=f"(hi) : "l"(in))

__global__ __launch_bounds__(BLOCK, 1)
void quanv_fused_kernel(const float* __restrict__ x,
                        const float* __restrict__ emb_W,
                        const float* __restrict__ emb_b,
                        const float* __restrict__ q_params,
                        const float* __restrict__ lin_W,
                        const float* __restrict__ lin_b,
                        float* __restrict__ out,
                        int B)
{
    const int warp = threadIdx.x >> 5;
    const int lane = threadIdx.x & 31;
    const int b    = blockIdx.x * WPB + warp;
    if (b >= B) return;

    // ---- uniform circuit constants (broadcast loads + MUFU) ----
    const float Kc0 = __cosf(q_params[0]);           // cos q0
    const float Kq1 = q_params[1];                   // q1
    float s4, c4;
    __sincosf(q_params[4], &s4, &c4);                // sin/cos q4
    const float Ks4 = s4 * __cosf(q_params[2]);      // sin q4 * cos q2
    const float Kc3 = __cosf(q_params[3]);           // cos q3

    const float4 W0 = __ldg((const float4*)(emb_W + 0));
    const float4 W1 = __ldg((const float4*)(emb_W + 4));
    const float4 W2 = __ldg((const float4*)(emb_W + 8));
    const float4 W3 = __ldg((const float4*)(emb_W + 12));
    const float4 eb = __ldg((const float4*)emb_b);

    const float*   xb  = x + b * 784;
    const double2* lw2 = (const double2*)lin_W;  // lw2[c*196 + p]

    // per-lane patch ids: p = lane + 32k for k<6; tail round uses clamped 192+min(lane,3)
    const bool tl = (lane < 4);
    const int  pt = 192 + (tl ? lane : 0);       // valid address for all lanes

    // ---- phase A: front-batch ALL image loads (MLP = 14) ----
    float2 tp[7], bt[7];
#pragma unroll
    for (int k = 0; k < 7; k++) {
        const int p  = (k < 6) ? (lane + 32 * k) : pt;
        const int pr = p / 14, pc = p % 14;
        tp[k] = *(const float2*)(xb + (2 * pr) * 28 + 2 * pc);
        bt[k] = *(const float2*)(xb + (2 * pr + 1) * 28 + 2 * pc);
    }

    // ---- phase B: all features (independent rounds, pipelined MUFU) ----
    unsigned long long E01[7], E23[7];
#pragma unroll
    for (int k = 0; k < 7; k++) {
        const float2 T = tp[k], Bt = bt[k];
        const float a0 = fmaf(T.x, W0.x, fmaf(T.y, W0.y, fmaf(Bt.x, W0.z, fmaf(Bt.y, W0.w, eb.x))));
        const float a1 = fmaf(T.x, W1.x, fmaf(T.y, W1.y, fmaf(Bt.x, W1.z, fmaf(Bt.y, W1.w, eb.y))));
        const float a2 = fmaf(T.x, W2.x, fmaf(T.y, W2.y, fmaf(Bt.x, W2.z, fmaf(Bt.y, W2.w, eb.z))));
        const float a3 = fmaf(T.x, W3.x, fmaf(T.y, W3.y, fmaf(Bt.x, W3.z, fmaf(Bt.y, W3.w, eb.w))));

        const float ca0  = __cosf(a0);
        const float ca1q = __cosf(a1 + Kq1);
        float sa2, ca2, sa3, ca3;
        __sincosf(a2, &sa2, &ca2);
        __sincosf(a3, &sa3, &ca3);

        float e0 = Kc0 * ca0;
        float e1 = e0 * ca1q;
        float e2 = e1 * fmaf(c4, ca2, -Ks4 * sa2 * sa3);
        float e3 = ca2 * (Kc3 * ca3);

        if (k == 6 && !tl) { e0 = 0.f; e1 = 0.f; e2 = 0.f; e3 = 0.f; }

        PACK_F32X2(E01[k], e0, e1);
        PACK_F32X2(E23[k], e2, e3);
    }

    // ---- phase C: GEMV, 10 independent accumulator chains, deep load batching ----
    float acc[10];
#pragma unroll
    for (int c = 0; c < 10; c++) {
        unsigned long long a2v = 0ull;
#pragma unroll
        for (int k = 0; k < 7; k++) {
            const int p = (k < 6) ? (lane + 32 * k) : pt;
            const double2 wd = __ldg(&lw2[c * NPATCH + p]);
            const unsigned long long wxy = __double_as_longlong(wd.x);
            const unsigned long long wzw = __double_as_longlong(wd.y);
            FMA_F32X2(a2v, E23[k], wzw, a2v);
            FMA_F32X2(a2v, E01[k], wxy, a2v);
        }
        float lo, hi;
        UNPACK_F32X2(lo, hi, a2v);
        acc[c] = lo + hi;
    }

    // ---- xor-butterfly: every lane ends with the full 10 logit sums ----
#pragma unroll
    for (int off = 16; off > 0; off >>= 1)
#pragma unroll
        for (int c = 0; c < 10; c++)
            acc[c] += __shfl_xor_sync(0xffffffffu, acc[c], off);

    // ---- log_softmax, lanes 0..9 write coalesced ----
    if (lane < 10) {
        float lg[10];
#pragma unroll
        for (int c = 0; c < 10; c++) lg[c] = acc[c] + __ldg(&lin_b[c]);

        float mx = lg[0];
#pragma unroll
        for (int c = 1; c < 10; c++) mx = fmaxf(mx, lg[c]);
        float se = 0.f;
#pragma unroll
        for (int c = 0; c < 10; c++) se += __expf(lg[c] - mx);
        const float lse = mx + __logf(se);

        float v = lg[0];
#pragma unroll
        for (int c = 1; c < 10; c++) if (lane == c) v = lg[c];
        out[b * 10 + lane] = v - lse;
    }
}

extern "C" void kernel_launch(void* const* d_in, const int* in_sizes, int n_in,
                              void* d_out, int out_size)
{
    const float* x        = (const float*)d_in[0];
    const float* emb_W    = (const float*)d_in[1];
    const float* emb_b    = (const float*)d_in[2];
    const float* q_params = (const float*)d_in[3];
    const float* lin_W    = (const float*)d_in[4];
    const float* lin_b    = (const float*)d_in[5];
    float* out = (float*)d_out;

    const int B = in_sizes[0] / 784;
    const int grid = (B + WPB - 1) / WPB;
    quanv_fused_kernel<<<grid, BLOCK>>>(x, emb_W, emb_b, q_params, lin_W, lin_b, out, B);
}

// round 10
// speedup vs baseline: 1.4261x; 1.1512x over previous
#include <cuda_runtime.h>
#include <math.h>
#include <cstdint>

#define NPATCH 196
#define WPB    2      // images (warps) per block
#define BLOCK  (WPB * 32)

#define FMA_F32X2(d, a, b, c) \
    asm("fma.rn.f32x2 %0, %1, %2, %3;" : "=l"(d) : "l"(a), "l"(b), "l"(c))
#define PACK_F32X2(out, lo, hi) \
    asm("mov.b64 %0, {%1, %2};" : "=l"(out) : "f"(lo), "f"(hi))
#define UNPACK_F32X2(lo, hi, in) \
    asm("mov.b64 {%0, %1}, %2;" : "=f"(lo), "=f"(hi) : "l"(in))

__global__ __launch_bounds__(BLOCK, 7)   // cap regs ~146 -> 14 warps/SM, single wave
void quanv_fused_kernel(const float* __restrict__ x,
                        const float* __restrict__ emb_W,
                        const float* __restrict__ emb_b,
                        const float* __restrict__ q_params,
                        const float* __restrict__ lin_W,
                        const float* __restrict__ lin_b,
                        float* __restrict__ out,
                        int B)
{
    const int warp = threadIdx.x >> 5;
    const int lane = threadIdx.x & 31;
    const int b    = blockIdx.x * WPB + warp;
    if (b >= B) return;

    // ---- uniform circuit constants (broadcast loads + MUFU) ----
    const float Kc0 = __cosf(q_params[0]);           // cos q0
    const float Kq1 = q_params[1];                   // q1
    float s4, c4;
    __sincosf(q_params[4], &s4, &c4);                // sin/cos q4
    const float Ks4 = s4 * __cosf(q_params[2]);      // sin q4 * cos q2
    const float Kc3 = __cosf(q_params[3]);           // cos q3

    const float4 W0 = __ldg((const float4*)(emb_W + 0));
    const float4 W1 = __ldg((const float4*)(emb_W + 4));
    const float4 W2 = __ldg((const float4*)(emb_W + 8));
    const float4 W3 = __ldg((const float4*)(emb_W + 12));
    const float4 eb = __ldg((const float4*)emb_b);

    const float*   xb  = x + b * 784;
    const double2* lw2 = (const double2*)lin_W;  // lw2[c*196 + p]

    // per-lane patch ids: p = lane + 32k for k<6; tail round uses clamped 192+min(lane,3)
    const bool tl = (lane < 4);
    const int  pt = 192 + (tl ? lane : 0);       // valid address for all lanes

    // ---- phase A: front-batch ALL image loads (MLP = 14) ----
    float2 tp[7], bt[7];
#pragma unroll
    for (int k = 0; k < 7; k++) {
        const int p  = (k < 6) ? (lane + 32 * k) : pt;
        const int pr = p / 14, pc = p % 14;
        tp[k] = *(const float2*)(xb + (2 * pr) * 28 + 2 * pc);
        bt[k] = *(const float2*)(xb + (2 * pr + 1) * 28 + 2 * pc);
    }

    // ---- phase B: all features (independent rounds, pipelined MUFU) ----
    unsigned long long E01[7], E23[7];
#pragma unroll
    for (int k = 0; k < 7; k++) {
        const float2 T = tp[k], Bt = bt[k];
        const float a0 = fmaf(T.x, W0.x, fmaf(T.y, W0.y, fmaf(Bt.x, W0.z, fmaf(Bt.y, W0.w, eb.x))));
        const float a1 = fmaf(T.x, W1.x, fmaf(T.y, W1.y, fmaf(Bt.x, W1.z, fmaf(Bt.y, W1.w, eb.y))));
        const float a2 = fmaf(T.x, W2.x, fmaf(T.y, W2.y, fmaf(Bt.x, W2.z, fmaf(Bt.y, W2.w, eb.z))));
        const float a3 = fmaf(T.x, W3.x, fmaf(T.y, W3.y, fmaf(Bt.x, W3.z, fmaf(Bt.y, W3.w, eb.w))));

        const float ca0  = __cosf(a0);
        const float ca1q = __cosf(a1 + Kq1);
        float sa2, ca2, sa3, ca3;
        __sincosf(a2, &sa2, &ca2);
        __sincosf(a3, &sa3, &ca3);

        float e0 = Kc0 * ca0;
        float e1 = e0 * ca1q;
        float e2 = e1 * fmaf(c4, ca2, -Ks4 * sa2 * sa3);
        float e3 = ca2 * (Kc3 * ca3);

        if (k == 6 && !tl) { e0 = 0.f; e1 = 0.f; e2 = 0.f; e3 = 0.f; }

        PACK_F32X2(E01[k], e0, e1);
        PACK_F32X2(E23[k], e2, e3);
    }

    // ---- phase C: GEMV, 10 independent accumulator chains ----
    float acc[10];
#pragma unroll
    for (int c = 0; c < 10; c++) {
        unsigned long long a2v = 0ull;
#pragma unroll
        for (int k = 0; k < 7; k++) {
            const int p = (k < 6) ? (lane + 32 * k) : pt;
            const double2 wd = __ldg(&lw2[c * NPATCH + p]);
            const unsigned long long wxy = __double_as_longlong(wd.x);
            const unsigned long long wzw = __double_as_longlong(wd.y);
            FMA_F32X2(a2v, E23[k], wzw, a2v);
            FMA_F32X2(a2v, E01[k], wxy, a2v);
        }
        float lo, hi;
        UNPACK_F32X2(lo, hi, a2v);
        acc[c] = lo + hi;
    }

    // ---- xor-butterfly: every lane ends with the full 10 logit sums ----
#pragma unroll
    for (int off = 16; off > 0; off >>= 1)
#pragma unroll
        for (int c = 0; c < 10; c++)
            acc[c] += __shfl_xor_sync(0xffffffffu, acc[c], off);

    // ---- log_softmax, lanes 0..9 write coalesced ----
    if (lane < 10) {
        float lg[10];
#pragma unroll
        for (int c = 0; c < 10; c++) lg[c] = acc[c] + __ldg(&lin_b[c]);

        float mx = lg[0];
#pragma unroll
        for (int c = 1; c < 10; c++) mx = fmaxf(mx, lg[c]);
        float se = 0.f;
#pragma unroll
        for (int c = 0; c < 10; c++) se += __expf(lg[c] - mx);
        const float lse = mx + __logf(se);

        float v = lg[0];
#pragma unroll
        for (int c = 1; c < 10; c++) if (lane == c) v = lg[c];
        out[b * 10 + lane] = v - lse;
    }
}

extern "C" void kernel_launch(void* const* d_in, const int* in_sizes, int n_in,
                              void* d_out, int out_size)
{
    const float* x        = (const float*)d_in[0];
    const float* emb_W    = (const float*)d_in[1];
    const float* emb_b    = (const float*)d_in[2];
    const float* q_params = (const float*)d_in[3];
    const float* lin_W    = (const float*)d_in[4];
    const float* lin_b    = (const float*)d_in[5];
    float* out = (float*)d_out;

    const int B = in_sizes[0] / 784;
    const int grid = (B + WPB - 1) / WPB;
    quanv_fused_kernel<<<grid, BLOCK>>>(x, emb_W, emb_b, q_params, lin_W, lin_b, out, B);
}